// round 14
// baseline (speedup 1.0000x reference)
#include <cuda_runtime.h>
#include <cstdint>

// Correlation layer: out[b, (dy+4)*9+(dx+4), y, x] =
//   (1/C) * sum_c first[b,c,y,x] * second[b,c,y+dy,x+dx]   (zero-padded)
// B=8, C=256, H=96, W=160, MAX_DISP=4 -> 81 displacements.
//
// R13 = R7 tiling + compute mapping (unchanged, measured-good)
//       + R12's compact row-per-thread staging (low regs)
//       + __launch_bounds__(144,4): 4 CTAs/SM -> 18 live warps.

#define MAXD    4
#define NDISP   9
#define BATCH   8
#define CHN     256
#define HH      96
#define WW      160
#define HW      (HH*WW)

#define TY      4
#define TX      32
#define PX      8
#define CH      8
#define NITER   (CHN/CH)       // 32

#define BROWS   (TY + 2*MAXD)  // 12
#define BSTR    44             // padded B row stride (floats)
#define ASTR    36             // padded A row stride (floats)
#define BTILEP  (BROWS*BSTR)   // 528 floats per channel
#define ATILEP  (TY*ASTR)      // 144 floats per channel
#define BUF_FLOATS (CH*(BTILEP+ATILEP))   // 5376 floats
#define BUF_BYTES  (BUF_FLOATS*4)         // 21504 B
#define SMEM_BYTES (2*BUF_BYTES)          // 43008 B

#define NTHREADS 144           // 4 xg * 4 yy * 9 w

__device__ __forceinline__ uint32_t smem_u32(const void* p) {
    return (uint32_t)__cvta_generic_to_shared(p);
}
__device__ __forceinline__ void cp16(uint32_t s, const void* g, int srcsz) {
    asm volatile("cp.async.cg.shared.global [%0], [%1], 16, %2;\n"
                 :: "r"(s), "l"(g), "r"(srcsz));
}
__device__ __forceinline__ void cp_commit() {
    asm volatile("cp.async.commit_group;\n" ::: "memory");
}
template<int N>
__device__ __forceinline__ void cp_wait() {
    asm volatile("cp.async.wait_group %0;\n" :: "n"(N) : "memory");
}

extern __shared__ float smem[];

__global__ __launch_bounds__(NTHREADS, 4)
void corr_kernel(const float* __restrict__ first,
                 const float* __restrict__ second,
                 float* __restrict__ out)
{
    const int xt  = blockIdx.x * TX;
    const int y0  = blockIdx.y * TY;
    const int b   = blockIdx.z;
    const int tid = threadIdx.x;

    const size_t base = (size_t)b * CHN * HW;
    const uint32_t smem0 = smem_u32(smem);

    // ---- compact staging descriptor: one halo/tile ROW per thread ----
    //   tid  0..95  : B halo row  (c = tid/12, r = tid%12), 10 float4
    //   tid 96..127 : A tile row  (c = (tid-96)>>2, r = (tid-96)&3), 8 float4
    //   tid 128..143: idle during staging
    const char* rp = (const char*)first;   // gmem byte ptr for this row
    uint32_t    sa = smem0;                // smem byte addr (buffer 0)
    uint32_t    mask = 0;                  // per-float4 validity bits
    int         nq = 0;                    // float4 count (10 B / 8 A / 0 idle)

    if (tid < 96) {
        const int c  = tid / 12;
        const int r  = tid - 12 * c;
        const int gy = y0 - MAXD + r;
        sa = smem0 + (uint32_t)(c * BTILEP + r * BSTR) * 4u;
        uint32_t m = 0x3FFu;                       // 10 float4: gx = xt-4+4q
        if (xt == 0)           m &= 0x3FEu;        // q=0 OOB left
        if (xt == WW - TX)     m &= 0x1FFu;        // q=9 OOB right
        const bool yok = (unsigned)gy < (unsigned)HH;
        mask = yok ? m : 0u;
        rp = yok ? (const char*)(second + base + ((size_t)c * HH + gy) * WW + (xt - MAXD))
                 : (const char*)(second + base);   // safe base, all srcsz=0
        nq = 10;
    } else if (tid < 128) {
        const int j = tid - 96;
        const int c = j >> 2;
        const int r = j & 3;
        sa = smem0 + (uint32_t)(CH * BTILEP + c * ATILEP + r * ASTR) * 4u;
        rp = (const char*)(first + base + ((size_t)c * HH + y0 + r) * WW + xt);
        mask = 0xFFu;
        nq = 8;
    }

#define STAGE_STEP(soff)                                                      \
    do {                                                                      \
        _Pragma("unroll")                                                     \
        for (int q = 0; q < 10; ++q)                                          \
            if (q < nq) {                                                     \
                const uint32_t ok_ = (mask >> q) & 1u;                        \
                cp16(sa + (soff) + 16u * q,                                   \
                     ok_ ? rp + 16 * q : rp + 80, (int)(ok_ << 4));           \
            }                                                                 \
        rp += (size_t)CH * HW * sizeof(float);                                \
    } while (0)

    // ---- compute-role mapping (R7, measured-good) ----
    const int xg = tid & 3;           // 8-pixel x-strip
    const int yy = (tid >> 2) & 3;    // row within tile
    const int w  = tid >> 4;          // dy index 0..8 (two per warp -> broadcast)

    float acc[PX][NDISP];             // 72 accumulators
    #pragma unroll
    for (int i = 0; i < PX; ++i)
        #pragma unroll
        for (int j = 0; j < NDISP; ++j)
            acc[i][j] = 0.0f;

    // ---- prologue: stage chunk 0 ----
    STAGE_STEP(0u);
    cp_commit();

    uint32_t buf = 0;
    #pragma unroll 1
    for (int it = 0; it < NITER; ++it) {
        if (it + 1 < NITER) {
            STAGE_STEP((buf ^ 1u) * BUF_BYTES);
            cp_commit();
            cp_wait<1>();
        } else {
            cp_wait<0>();
        }
        __syncthreads();

        const float* Bb = smem + buf * BUF_FLOATS;
        const float* Ab = Bb + CH * BTILEP;
        #pragma unroll
        for (int cc = 0; cc < CH; ++cc) {
            const float* arow = &Ab[cc * ATILEP + yy * ASTR + 8 * xg];
            const float4 a0 = *reinterpret_cast<const float4*>(arow);
            const float4 a1 = *reinterpret_cast<const float4*>(arow + 4);

            // Pixel p = 8*xg+i uses halo cols 8*xg .. 8*xg+15 of row yy+w
            const float* brow = &Bb[cc * BTILEP + (yy + w) * BSTR + 8 * xg];
            const float4 b0 = *reinterpret_cast<const float4*>(brow);
            const float4 b1 = *reinterpret_cast<const float4*>(brow + 4);
            const float4 b2 = *reinterpret_cast<const float4*>(brow + 8);
            const float4 b3 = *reinterpret_cast<const float4*>(brow + 12);

            const float a[PX]  = {a0.x, a0.y, a0.z, a0.w,
                                  a1.x, a1.y, a1.z, a1.w};
            const float bv[16] = {b0.x, b0.y, b0.z, b0.w,
                                  b1.x, b1.y, b1.z, b1.w,
                                  b2.x, b2.y, b2.z, b2.w,
                                  b3.x, b3.y, b3.z, b3.w};
            #pragma unroll
            for (int i = 0; i < PX; ++i)
                #pragma unroll
                for (int j = 0; j < NDISP; ++j)
                    acc[i][j] = fmaf(a[i], bv[i + j], acc[i][j]);
        }
        __syncthreads();
        buf ^= 1u;
    }

    // ---- epilogue: mean over C, float4-pair stores ----
    const float scale = 1.0f / (float)CHN;
    const int y = y0 + yy;
    const int x = xt + 8 * xg;
    #pragma unroll
    for (int j = 0; j < NDISP; ++j) {
        const int d = w * NDISP + j;
        float* orow = &out[(((size_t)b * 81 + d) * HH + y) * WW + x];
        float4 o0, o1;
        o0.x = acc[0][j] * scale; o0.y = acc[1][j] * scale;
        o0.z = acc[2][j] * scale; o0.w = acc[3][j] * scale;
        o1.x = acc[4][j] * scale; o1.y = acc[5][j] * scale;
        o1.z = acc[6][j] * scale; o1.w = acc[7][j] * scale;
        *reinterpret_cast<float4*>(orow)     = o0;
        *reinterpret_cast<float4*>(orow + 4) = o1;
    }
}

extern "C" void kernel_launch(void* const* d_in, const int* in_sizes, int n_in,
                              void* d_out, int out_size)
{
    const float* first  = (const float*)d_in[0];
    const float* second = (const float*)d_in[1];
    float* out          = (float*)d_out;

    // Idempotent, deterministic, not stream-ordered (capture-safe).
    cudaFuncSetAttribute(corr_kernel,
                         cudaFuncAttributeMaxDynamicSharedMemorySize, SMEM_BYTES);
    cudaFuncSetAttribute(corr_kernel,
                         cudaFuncAttributePreferredSharedMemoryCarveout, 100);

    dim3 grid(WW / TX, HH / TY, BATCH);   // (5, 24, 8)
    dim3 block(NTHREADS);
    corr_kernel<<<grid, block, SMEM_BYTES>>>(first, second, out);
}

// round 15
// speedup vs baseline: 1.8993x; 1.8993x over previous
#include <cuda_runtime.h>
#include <cuda.h>
#include <cstdint>

// Correlation layer: out[b, (dy+4)*9+(dx+4), y, x] =
//   (1/C) * sum_c first[b,c,y,x] * second[b,c,y+dy,x+dx]   (zero-padded)
// B=8, C=256, H=96, W=160, MAX_DISP=4 -> 81 displacements.
//
// R15 = R7 compute (verbatim, measured-good) + TMA staging:
//   two cp.async.bulk.tensor.3d loads per channel chunk (A tile, B halo),
//   issued by thread 0, double-buffered on mbarriers. TMA box widths 36/44
//   reproduce R7's padded smem strides; OOB rows/cols zero-fill the halo.

#define MAXD    4
#define NDISP   9
#define BATCH   8
#define CHN     256
#define HH      96
#define WW      160
#define HW      (HH*WW)

#define TY      4
#define TX      32
#define PX      8
#define CH      8
#define NITER   (CHN/CH)       // 32

#define BROWS   (TY + 2*MAXD)  // 12
#define BSTR    44             // B row stride = TMA box0 (4 pad cols, never read)
#define ASTR    36             // A row stride = TMA box0
#define BTILEP  (BROWS*BSTR)   // 528 floats per channel
#define ATILEP  (TY*ASTR)      // 144 floats per channel
#define BUF_FLOATS (CH*(BTILEP+ATILEP))   // 5376 floats
#define BUF_BYTES  (BUF_FLOATS*4)         // 21504 B (TMA tx per chunk)
#define MBAR_REGION 128                   // bytes reserved for 2 mbarriers
#define SMEM_BYTES (MBAR_REGION + 2*BUF_BYTES)   // 43136 B

#define NTHREADS 144           // 4 xg * 4 yy * 9 w

__device__ __forceinline__ uint32_t smem_u32(const void* p) {
    return (uint32_t)__cvta_generic_to_shared(p);
}
__device__ __forceinline__ void mbar_init(uint32_t addr, uint32_t count) {
    asm volatile("mbarrier.init.shared::cta.b64 [%0], %1;"
                 :: "r"(addr), "r"(count) : "memory");
}
__device__ __forceinline__ void mbar_expect_tx(uint32_t addr, uint32_t bytes) {
    asm volatile("mbarrier.arrive.expect_tx.shared::cta.b64 _, [%0], %1;"
                 :: "r"(addr), "r"(bytes) : "memory");
}
__device__ __forceinline__ void mbar_wait(uint32_t addr, uint32_t parity) {
    asm volatile(
        "{\n\t.reg .pred P;\n\t"
        "W%=:\n\t"
        "mbarrier.try_wait.parity.shared::cta.b64 P, [%0], %1;\n\t"
        "@!P bra W%=;\n\t}"
        :: "r"(addr), "r"(parity) : "memory");
}
__device__ __forceinline__ void tma3d(uint32_t dst, const CUtensorMap* map,
                                      int x, int y, int z, uint32_t mbar) {
    asm volatile(
        "cp.async.bulk.tensor.3d.shared::cta.global.tile.mbarrier::complete_tx::bytes "
        "[%0], [%1, {%2, %3, %4}], [%5];"
        :: "r"(dst), "l"(map), "r"(x), "r"(y), "r"(z), "r"(mbar) : "memory");
}
__device__ __forceinline__ void fence_async() {
    asm volatile("fence.proxy.async.shared::cta;" ::: "memory");
}

extern __shared__ float smem[];

__global__ __launch_bounds__(NTHREADS, 3)
void corr_kernel(const __grid_constant__ CUtensorMap tmA,
                 const __grid_constant__ CUtensorMap tmB,
                 float* __restrict__ out)
{
    const uint32_t smem0 = smem_u32(smem);     // mbar[0] @ +0, mbar[1] @ +8
    float* bufs = smem + MBAR_REGION / 4;
    const uint32_t bufs0 = smem0 + MBAR_REGION;

    const int xt  = blockIdx.x * TX;
    const int y0  = blockIdx.y * TY;
    const int b   = blockIdx.z;
    const int tid = threadIdx.x;
    const int zb  = b * CHN;

    if (tid == 0) {
        mbar_init(smem0 + 0, 1);
        mbar_init(smem0 + 8, 1);
        fence_async();
    }
    __syncthreads();

    // ---- prologue: stage chunks 0 and 1 (lookahead 2) ----
    if (tid == 0) {
        mbar_expect_tx(smem0 + 0, BUF_BYTES);
        tma3d(bufs0,                     &tmB, xt - MAXD, y0 - MAXD, zb,      smem0 + 0);
        tma3d(bufs0 + CH * BTILEP * 4,   &tmA, xt,        y0,        zb,      smem0 + 0);
        mbar_expect_tx(smem0 + 8, BUF_BYTES);
        tma3d(bufs0 + BUF_BYTES,                   &tmB, xt - MAXD, y0 - MAXD, zb + CH, smem0 + 8);
        tma3d(bufs0 + BUF_BYTES + CH * BTILEP * 4, &tmA, xt,        y0,        zb + CH, smem0 + 8);
    }

    // ---- compute-role mapping (R7, measured-good) ----
    const int xg = tid & 3;           // 8-pixel x-strip
    const int yy = (tid >> 2) & 3;    // row within tile
    const int w  = tid >> 4;          // dy index 0..8 (two per warp -> broadcast)

    float acc[PX][NDISP];             // 72 accumulators
    #pragma unroll
    for (int i = 0; i < PX; ++i)
        #pragma unroll
        for (int j = 0; j < NDISP; ++j)
            acc[i][j] = 0.0f;

    int ph0 = 0, ph1 = 0;
    #pragma unroll 1
    for (int it = 0; it < NITER; ++it) {
        const int buf = it & 1;
        if (buf == 0) { mbar_wait(smem0 + 0, ph0); ph0 ^= 1; }
        else          { mbar_wait(smem0 + 8, ph1); ph1 ^= 1; }

        const float* Bb = bufs + buf * BUF_FLOATS;
        const float* Ab = Bb + CH * BTILEP;
        #pragma unroll
        for (int cc = 0; cc < CH; ++cc) {
            const float* arow = &Ab[cc * ATILEP + yy * ASTR + 8 * xg];
            const float4 a0 = *reinterpret_cast<const float4*>(arow);
            const float4 a1 = *reinterpret_cast<const float4*>(arow + 4);

            // Pixel p = 8*xg+i uses halo cols 8*xg .. 8*xg+15 of row yy+w
            const float* brow = &Bb[cc * BTILEP + (yy + w) * BSTR + 8 * xg];
            const float4 b0 = *reinterpret_cast<const float4*>(brow);
            const float4 b1 = *reinterpret_cast<const float4*>(brow + 4);
            const float4 b2 = *reinterpret_cast<const float4*>(brow + 8);
            const float4 b3 = *reinterpret_cast<const float4*>(brow + 12);

            const float a[PX]  = {a0.x, a0.y, a0.z, a0.w,
                                  a1.x, a1.y, a1.z, a1.w};
            const float bv[16] = {b0.x, b0.y, b0.z, b0.w,
                                  b1.x, b1.y, b1.z, b1.w,
                                  b2.x, b2.y, b2.z, b2.w,
                                  b3.x, b3.y, b3.z, b3.w};
            #pragma unroll
            for (int i = 0; i < PX; ++i)
                #pragma unroll
                for (int j = 0; j < NDISP; ++j)
                    acc[i][j] = fmaf(a[i], bv[i + j], acc[i][j]);
        }

        __syncthreads();              // all threads done reading this buffer
        if (it + 2 < NITER && tid == 0) {
            fence_async();            // order prior generic reads vs async writes
            const uint32_t mb  = smem0 + 8u * (uint32_t)buf;
            const uint32_t dst = bufs0 + (uint32_t)buf * BUF_BYTES;
            const int z = zb + (it + 2) * CH;
            mbar_expect_tx(mb, BUF_BYTES);
            tma3d(dst,                   &tmB, xt - MAXD, y0 - MAXD, z, mb);
            tma3d(dst + CH * BTILEP * 4, &tmA, xt,        y0,        z, mb);
        }
    }

    // ---- epilogue: mean over C, float4-pair stores ----
    const float scale = 1.0f / (float)CHN;
    const int y = y0 + yy;
    const int x = xt + 8 * xg;
    #pragma unroll
    for (int j = 0; j < NDISP; ++j) {
        const int d = w * NDISP + j;
        float* orow = &out[(((size_t)b * 81 + d) * HH + y) * WW + x];
        float4 o0, o1;
        o0.x = acc[0][j] * scale; o0.y = acc[1][j] * scale;
        o0.z = acc[2][j] * scale; o0.w = acc[3][j] * scale;
        o1.x = acc[4][j] * scale; o1.y = acc[5][j] * scale;
        o1.z = acc[6][j] * scale; o1.w = acc[7][j] * scale;
        *reinterpret_cast<float4*>(orow)     = o0;
        *reinterpret_cast<float4*>(orow + 4) = o1;
    }
}

// ---- host side ----

typedef CUresult (*PFN_encodeTiled)(
    CUtensorMap*, CUtensorMapDataType, cuuint32_t, void*,
    const cuuint64_t*, const cuuint64_t*, const cuuint32_t*, const cuuint32_t*,
    CUtensorMapInterleave, CUtensorMapSwizzle, CUtensorMapL2promotion,
    CUtensorMapFloatOOBfill);

extern "C" void kernel_launch(void* const* d_in, const int* in_sizes, int n_in,
                              void* d_out, int out_size)
{
    float* first  = (float*)d_in[0];
    float* second = (float*)d_in[1];
    float* out    = (float*)d_out;

    // Driver entry point via runtime API (no -lcuda link needed).
    PFN_encodeTiled encode = nullptr;
    cudaDriverEntryPointQueryResult qr;
    cudaGetDriverEntryPointByVersion("cuTensorMapEncodeTiled",
                                     (void**)&encode, 12000,
                                     cudaEnableDefault, &qr);
    if (!encode) return;   // fail loudly via wrong output rather than crash

    // Global view for both tensors: (W, H, C*B) fp32, row-major.
    cuuint64_t dims[3]    = {WW, HH, (cuuint64_t)CHN * BATCH};
    cuuint64_t strides[2] = {(cuuint64_t)WW * 4, (cuuint64_t)HW * 4};
    cuuint32_t elemstr[3] = {1, 1, 1};
    cuuint32_t boxA[3] = {ASTR, TY,    CH};   // 36 x 4 x 8
    cuuint32_t boxB[3] = {BSTR, BROWS, CH};   // 44 x 12 x 8

    CUtensorMap tmA, tmB;
    encode(&tmA, CU_TENSOR_MAP_DATA_TYPE_FLOAT32, 3, (void*)first,
           dims, strides, boxA, elemstr,
           CU_TENSOR_MAP_INTERLEAVE_NONE, CU_TENSOR_MAP_SWIZZLE_NONE,
           CU_TENSOR_MAP_L2_PROMOTION_L2_128B, CU_TENSOR_MAP_FLOAT_OOB_FILL_NONE);
    encode(&tmB, CU_TENSOR_MAP_DATA_TYPE_FLOAT32, 3, (void*)second,
           dims, strides, boxB, elemstr,
           CU_TENSOR_MAP_INTERLEAVE_NONE, CU_TENSOR_MAP_SWIZZLE_NONE,
           CU_TENSOR_MAP_L2_PROMOTION_L2_128B, CU_TENSOR_MAP_FLOAT_OOB_FILL_NONE);

    // Idempotent, deterministic, not stream-ordered (capture-safe).
    cudaFuncSetAttribute(corr_kernel,
                         cudaFuncAttributeMaxDynamicSharedMemorySize, SMEM_BYTES);
    cudaFuncSetAttribute(corr_kernel,
                         cudaFuncAttributePreferredSharedMemoryCarveout, 100);

    dim3 grid(WW / TX, HH / TY, BATCH);   // (5, 24, 8)
    dim3 block(NTHREADS);
    corr_kernel<<<grid, block, SMEM_BYTES>>>(tmA, tmB, out);
}